// round 1
// baseline (speedup 1.0000x reference)
#include <cuda_runtime.h>
#include <cuda_bf16.h>

#define DIM 128

// ---------------------------------------------------------------------------
// Kernel A (sub2): one block per type node c. Edges for c are contiguous at
// [c*deg2, (c+1)*deg2). 128 threads, thread d owns dim d.
//   out[right_common[c]][d] = emb[right_common[c]][d]
//                           + sum_j emb[left_specific[sub2_row[c*deg2+j]]][d]
//                           + (n_ent - deg2)
// ---------------------------------------------------------------------------
__global__ void sub2_kernel(const float* __restrict__ emb,
                            const int* __restrict__ sub2_row,
                            const int* __restrict__ left_specific,
                            const int* __restrict__ right_common,
                            float* __restrict__ out,
                            int n_ent, int deg2) {
    extern __shared__ int rows[];
    const int c = blockIdx.x;
    const int d = threadIdx.x;  // 0..127

    for (int j = threadIdx.x; j < deg2; j += blockDim.x)
        rows[j] = left_specific[sub2_row[(size_t)c * deg2 + j]];
    __syncthreads();

    float acc = 0.0f;
    for (int j = 0; j < deg2; ++j)
        acc += emb[(size_t)rows[j] * DIM + d];

    const int rc = right_common[c];
    out[(size_t)rc * DIM + d] =
        emb[(size_t)rc * DIM + d] + acc + (float)(n_ent - deg2);
}

// ---------------------------------------------------------------------------
// Kernel B (sub3): one warp per entity node c. Edges contiguous at
// [c*deg3, (c+1)*deg3). Each lane holds one float4 (32 lanes x 4 = 128 dims).
// Type rows were updated into `out` by kernel A (all 1000 rows = 512KB,
// L2-resident). Entity row read from original emb (disjoint from updated
// type rows), streamed, then scaled and written back.
//   sum0 = sum_j out[left_common[sub3_row[c*deg3+j]]] + (n_typ - deg3)
//   out[right_specific[c]] = emb[right_specific[c]] * (1 - sum0/(1+deg3))
// ---------------------------------------------------------------------------
__global__ void sub3_kernel(const float* __restrict__ emb,
                            const int* __restrict__ sub3_row,
                            const int* __restrict__ left_common,
                            const int* __restrict__ right_specific,
                            float* out,
                            int n_ent, int n_typ, int deg3) {
    const int gw   = (int)((blockIdx.x * (size_t)blockDim.x + threadIdx.x) >> 5);
    const int lane = threadIdx.x & 31;
    if (gw >= n_ent) return;

    const float addc = (float)(n_typ - deg3);
    const float inv  = 1.0f / (float)(1 + deg3);

    float4 acc = make_float4(0.f, 0.f, 0.f, 0.f);
    const int* rbase = sub3_row + (size_t)gw * deg3;
#pragma unroll 4
    for (int j = 0; j < deg3; ++j) {
        const int node = left_common[rbase[j]];           // uniform per warp -> bcast
        const float4 v = __ldg((const float4*)(out + (size_t)node * DIM) + lane);
        acc.x += v.x; acc.y += v.y; acc.z += v.z; acc.w += v.w;
    }

    const int rs = right_specific[gw];
    const float4 e = __ldg((const float4*)(emb + (size_t)rs * DIM) + lane);

    float4 r;
    r.x = e.x * (1.0f - (acc.x + addc) * inv);
    r.y = e.y * (1.0f - (acc.y + addc) * inv);
    r.z = e.z * (1.0f - (acc.z + addc) * inv);
    r.w = e.w * (1.0f - (acc.w + addc) * inv);

    ((float4*)(out + (size_t)rs * DIM) + lane)[0] = r;
}

extern "C" void kernel_launch(void* const* d_in, const int* in_sizes, int n_in,
                              void* d_out, int out_size) {
    const float* emb            = (const float*)d_in[0];
    const int*   sub2_row       = (const int*)d_in[1];
    // d_in[2] = sub2_col (column-sorted contiguous; implied by edge index)
    const int*   sub3_row       = (const int*)d_in[3];
    // d_in[4] = sub3_col (column-sorted contiguous; implied by edge index)
    const int*   left_specific  = (const int*)d_in[5];
    const int*   right_common   = (const int*)d_in[6];
    const int*   left_common    = (const int*)d_in[7];
    const int*   right_specific = (const int*)d_in[8];
    float*       out            = (float*)d_out;

    const int n_ent = in_sizes[5];                 // 200000
    const int n_typ = in_sizes[7];                 // 1000
    const int deg2  = in_sizes[1] / n_typ;         // 64
    const int deg3  = in_sizes[3] / n_ent;         // 4

    // Phase 1: updated type rows -> out[type rows]
    sub2_kernel<<<n_typ, DIM, deg2 * (int)sizeof(int)>>>(
        emb, sub2_row, left_specific, right_common, out, n_ent, deg2);

    // Phase 2: updated entity rows -> out[entity rows] (reads phase-1 output)
    const int warps_per_block = 8;                 // 256 threads
    const int blocks = (n_ent + warps_per_block - 1) / warps_per_block;
    sub3_kernel<<<blocks, warps_per_block * 32>>>(
        emb, sub3_row, left_common, right_specific, out, n_ent, n_typ, deg3);
}

// round 4
// speedup vs baseline: 1.4055x; 1.4055x over previous
#include <cuda_runtime.h>
#include <cuda_bf16.h>

#define DIM 128

// ---------------------------------------------------------------------------
// Kernel A (sub2): one block (256 thr = 8 warps) per type node c.
// Edges for c contiguous at [c*deg2, (c+1)*deg2). Each warp sums a strided
// subset of edge rows (lane = float4 column), then smem tree-reduce.
//   out[rc] = emb[rc] + sum_j emb[left_specific[sub2_row[...]]] + (n_ent-deg2)
// ---------------------------------------------------------------------------
__global__ void sub2_kernel(const float* __restrict__ emb,
                            const int* __restrict__ sub2_row,
                            const int* __restrict__ left_specific,
                            const int* __restrict__ right_common,
                            float* __restrict__ out,
                            int n_ent, int deg2) {
    extern __shared__ char smem_raw[];
    int*    rows = (int*)smem_raw;                         // [deg2]
    float4* red  = (float4*)(smem_raw + ((deg2 * 4 + 127) & ~127)); // [8][32]

    const int c     = blockIdx.x;
    const int w     = threadIdx.x >> 5;
    const int lane  = threadIdx.x & 31;
    const int nwarp = blockDim.x >> 5;

    // Stage indices through smem (breaks the dependent-load chain).
    for (int j = threadIdx.x; j < deg2; j += blockDim.x)
        rows[j] = left_specific[__ldg(sub2_row + (size_t)c * deg2 + j)];
    __syncthreads();

    float4 acc = make_float4(0.f, 0.f, 0.f, 0.f);
    for (int j = w; j < deg2; j += nwarp) {
        const float4 v = __ldg((const float4*)(emb + (size_t)rows[j] * DIM) + lane);
        acc.x += v.x; acc.y += v.y; acc.z += v.z; acc.w += v.w;
    }
    red[w * 32 + lane] = acc;
    __syncthreads();

    if (w == 0) {
        float4 s = red[lane];
#pragma unroll
        for (int k = 1; k < 8; ++k) {
            const float4 v = red[k * 32 + lane];
            s.x += v.x; s.y += v.y; s.z += v.z; s.w += v.w;
        }
        const int   rc = right_common[c];
        const float a  = (float)(n_ent - deg2);
        const float4 e = __ldg((const float4*)(emb + (size_t)rc * DIM) + lane);
        float4 r;
        r.x = e.x + s.x + a; r.y = e.y + s.y + a;
        r.z = e.z + s.z + a; r.w = e.w + s.w + a;
        ((float4*)(out + (size_t)rc * DIM) + lane)[0] = r;
    }
}

// ---------------------------------------------------------------------------
// Kernel B (sub3), specialized deg3==4: each warp processes 4 entities.
// 16 lanes load the 16 edge indices coalesced; shuffle-broadcast the type
// node ids; issue 4 streaming entity loads (__ldcs, evict-first) + 16
// independent L2 type-row gathers (__ldg) before consuming. ~20 LDG.128 in
// flight per warp vs ~6 before.
//   out[rs] = emb[rs] * (1 - (sum_j type_row + (n_typ-deg3)) / (1+deg3))
// ---------------------------------------------------------------------------
__global__ void sub3_kernel_d4(const float* __restrict__ emb,
                               const int* __restrict__ sub3_row,
                               const int* __restrict__ left_common,
                               const int* __restrict__ right_specific,
                               float* out,
                               int n_ent, int n_typ) {
    const int wpb  = blockDim.x >> 5;
    const int gw   = blockIdx.x * wpb + (threadIdx.x >> 5);
    const int lane = threadIdx.x & 31;
    const int base = gw * 4;
    if (base >= n_ent) return;

    const float addc = (float)(n_typ - 4);
    const float inv  = 0.2f;                       // 1/(1+deg3)

    // Index stage: lanes 0-15 -> type node ids; lanes 16-19 -> entity ids.
    int node_l = 0;
    if (lane < 16 && base + (lane >> 2) < n_ent)
        node_l = left_common[__ldg(sub3_row + (size_t)base * 4 + lane)];
    int rs_l = 0;
    if (lane >= 16 && lane < 20 && base + (lane - 16) < n_ent)
        rs_l = right_specific[base + (lane - 16)];

    // Streaming entity loads first (longest latency, DRAM).
    int    rs[4];
    float4 ev[4];
#pragma unroll
    for (int e = 0; e < 4; ++e) {
        rs[e] = __shfl_sync(0xffffffffu, rs_l, 16 + e);
        if (base + e < n_ent)
            ev[e] = __ldcs((const float4*)(emb + (size_t)rs[e] * DIM) + lane);
    }

    // 16 independent L2 gathers of the (L2-resident) updated type rows.
    float4 acc[4];
#pragma unroll
    for (int e = 0; e < 4; ++e) acc[e] = make_float4(0.f, 0.f, 0.f, 0.f);
#pragma unroll
    for (int e = 0; e < 4; ++e) {
#pragma unroll
        for (int j = 0; j < 4; ++j) {
            const int node = __shfl_sync(0xffffffffu, node_l, e * 4 + j);
            if (base + e < n_ent) {
                const float4 v = __ldg((const float4*)(out + (size_t)node * DIM) + lane);
                acc[e].x += v.x; acc[e].y += v.y; acc[e].z += v.z; acc[e].w += v.w;
            }
        }
    }

#pragma unroll
    for (int e = 0; e < 4; ++e) {
        if (base + e >= n_ent) break;
        float4 r;
        r.x = ev[e].x * (1.0f - (acc[e].x + addc) * inv);
        r.y = ev[e].y * (1.0f - (acc[e].y + addc) * inv);
        r.z = ev[e].z * (1.0f - (acc[e].z + addc) * inv);
        r.w = ev[e].w * (1.0f - (acc[e].w + addc) * inv);
        __stcs((float4*)(out + (size_t)rs[e] * DIM) + lane, r);
    }
}

// Generic fallback (any deg3), one warp per entity.
__global__ void sub3_kernel_gen(const float* __restrict__ emb,
                                const int* __restrict__ sub3_row,
                                const int* __restrict__ left_common,
                                const int* __restrict__ right_specific,
                                float* out,
                                int n_ent, int n_typ, int deg3) {
    const int gw   = (int)((blockIdx.x * (size_t)blockDim.x + threadIdx.x) >> 5);
    const int lane = threadIdx.x & 31;
    if (gw >= n_ent) return;

    const float addc = (float)(n_typ - deg3);
    const float inv  = 1.0f / (float)(1 + deg3);

    float4 acc = make_float4(0.f, 0.f, 0.f, 0.f);
    const int* rbase = sub3_row + (size_t)gw * deg3;
    for (int j = 0; j < deg3; ++j) {
        const int node = left_common[__ldg(rbase + j)];
        const float4 v = __ldg((const float4*)(out + (size_t)node * DIM) + lane);
        acc.x += v.x; acc.y += v.y; acc.z += v.z; acc.w += v.w;
    }
    const int   rs = right_specific[gw];
    const float4 e = __ldcs((const float4*)(emb + (size_t)rs * DIM) + lane);
    float4 r;
    r.x = e.x * (1.0f - (acc.x + addc) * inv);
    r.y = e.y * (1.0f - (acc.y + addc) * inv);
    r.z = e.z * (1.0f - (acc.z + addc) * inv);
    r.w = e.w * (1.0f - (acc.w + addc) * inv);
    __stcs((float4*)(out + (size_t)rs * DIM) + lane, r);
}

extern "C" void kernel_launch(void* const* d_in, const int* in_sizes, int n_in,
                              void* d_out, int out_size) {
    const float* emb            = (const float*)d_in[0];
    const int*   sub2_row       = (const int*)d_in[1];
    const int*   sub3_row       = (const int*)d_in[3];
    const int*   left_specific  = (const int*)d_in[5];
    const int*   right_common   = (const int*)d_in[6];
    const int*   left_common    = (const int*)d_in[7];
    const int*   right_specific = (const int*)d_in[8];
    float*       out            = (float*)d_out;

    const int n_ent = in_sizes[5];                 // 200000
    const int n_typ = in_sizes[7];                 // 1000
    const int deg2  = in_sizes[1] / n_typ;         // 64
    const int deg3  = in_sizes[3] / n_ent;         // 4

    // Phase 1: updated type rows -> out[type rows]
    const int smem = ((deg2 * 4 + 127) & ~127) + 8 * 32 * (int)sizeof(float4);
    sub2_kernel<<<n_typ, 256, smem>>>(
        emb, sub2_row, left_specific, right_common, out, n_ent, deg2);

    // Phase 2: updated entity rows -> out[entity rows]
    if (deg3 == 4) {
        const int wpb = 8;                          // 256 threads, 4 entities/warp
        const int ent_per_block = wpb * 4;
        const int blocks = (n_ent + ent_per_block - 1) / ent_per_block;
        sub3_kernel_d4<<<blocks, wpb * 32>>>(
            emb, sub3_row, left_common, right_specific, out, n_ent, n_typ);
    } else {
        const int wpb = 8;
        const int blocks = (n_ent + wpb - 1) / wpb;
        sub3_kernel_gen<<<blocks, wpb * 32>>>(
            emb, sub3_row, left_common, right_specific, out, n_ent, n_typ, deg3);
    }
}